// round 10
// baseline (speedup 1.0000x reference)
#include <cuda_runtime.h>

// Two real 3x3 bilinear forms (observables Z0, Z1), padded to 20 floats:
//   z_k = (1, X0, Y0) * M_k * (1, X1, Y1)^T,  X = cos(pi*n), Y = sin(pi*n).
__device__ float g_M[20];        // written by prep_kernel
__constant__ float c_M[20];      // copied from g_M via captured memcpy node

// Prep: 12 threads compute all transcendentals in parallel into smem, then
// thread 0 does pure-FMA algebra: compose W = L2*L1*D (4x4 complex), reduce
// each observable <Z_k> to a real 3x3 bilinear form, write g_M.
__global__ void prep_kernel(const float* __restrict__ qw) {
    __shared__ float sc[12], ss[12];
    int t = threadIdx.x;
    if (t < 12) {
        int l = t / 6, rem = t % 6, w = rem / 3, k = rem % 3;
        float phi = qw[l * 6 + w * 3 + 0];
        float th  = qw[l * 6 + w * 3 + 1];
        float om  = qw[l * 6 + w * 3 + 2];
        float ang = (k == 0) ? 0.5f * th
                  : (k == 1) ? 0.5f * (phi + om)
                             : 0.5f * (phi - om);
        float s, c;
        __sincosf(ang, &s, &c);
        sc[t] = c; ss[t] = s;
    }
    __syncwarp();
    if (t != 0) return;

    float Wr[4][4] = {}, Wi[4][4] = {};
    // D = diag(1, -i, -i, -1): folds the -i factors of RX|0> amplitudes.
    Wr[0][0] = 1.f; Wi[1][1] = -1.f; Wi[2][2] = -1.f; Wr[3][3] = -1.f;

    for (int l = 0; l < 2; l++) {
        float gr[2][2][2], gi[2][2][2];
        for (int w = 0; w < 2; w++) {
            int base = l * 6 + w * 3;
            float ct = sc[base + 0], st = ss[base + 0];
            float ca = sc[base + 1], sa = ss[base + 1];
            float cb = sc[base + 2], sb = ss[base + 2];
            gr[w][0][0] =  ct * ca;  gi[w][0][0] = -ct * sa;
            gr[w][0][1] = -st * cb;  gi[w][0][1] = -st * sb;
            gr[w][1][0] =  st * cb;  gi[w][1][0] = -st * sb;
            gr[w][1][1] =  ct * ca;  gi[w][1][1] =  ct * sa;
        }

        float Tr[4][4], Ti[4][4], Ur[4][4], Ui[4][4];
        // Gate on qubit 0: T[(i,j)][m] = sum_{i'} g0[i][i'] * W[(i',j)][m]
        for (int i = 0; i < 2; i++)
            for (int j = 0; j < 2; j++)
                for (int m = 0; m < 4; m++) {
                    int r = i * 2 + j;
                    Tr[r][m] = gr[0][i][0]*Wr[j][m]   - gi[0][i][0]*Wi[j][m]
                             + gr[0][i][1]*Wr[2+j][m] - gi[0][i][1]*Wi[2+j][m];
                    Ti[r][m] = gr[0][i][0]*Wi[j][m]   + gi[0][i][0]*Wr[j][m]
                             + gr[0][i][1]*Wi[2+j][m] + gi[0][i][1]*Wr[2+j][m];
                }
        // Gate on qubit 1: U[(i,j)][m] = sum_{j'} g1[j][j'] * T[(i,j')][m]
        for (int i = 0; i < 2; i++)
            for (int j = 0; j < 2; j++)
                for (int m = 0; m < 4; m++) {
                    int r = i * 2 + j;
                    Ur[r][m] = gr[1][j][0]*Tr[i*2][m]   - gi[1][j][0]*Ti[i*2][m]
                             + gr[1][j][1]*Tr[i*2+1][m] - gi[1][j][1]*Ti[i*2+1][m];
                    Ui[r][m] = gr[1][j][0]*Ti[i*2][m]   + gi[1][j][0]*Tr[i*2][m]
                             + gr[1][j][1]*Ti[i*2+1][m] + gi[1][j][1]*Tr[i*2+1][m];
                }
        // CNOT(c=0,t=1): new[(i,j)] = old[(i, j^i)]
        // CNOT(c=1,t=0): new[(i,j)] = old[(i^j, j)]
        for (int i = 0; i < 2; i++)
            for (int j = 0; j < 2; j++)
                for (int m = 0; m < 4; m++) {
                    Tr[i*2+j][m] = Ur[i*2+(j^i)][m];
                    Ti[i*2+j][m] = Ui[i*2+(j^i)][m];
                }
        for (int i = 0; i < 2; i++)
            for (int j = 0; j < 2; j++)
                for (int m = 0; m < 4; m++) {
                    Wr[i*2+j][m] = Tr[(i^j)*2+j][m];
                    Wi[i*2+j][m] = Ti[(i^j)*2+j][m];
                }
    }

    // u_a*u_b in basis (1, X, Y): c^2=(1+X)/2, cs=Y/2, s^2=(1-X)/2
    const float Qu[2][2][3] = {
        { {0.5f, 0.5f, 0.f}, {0.f, 0.f, 0.5f} },
        { {0.f, 0.f, 0.5f},  {0.5f, -0.5f, 0.f} }
    };

    for (int obs = 0; obs < 2; obs++) {
        float s[4];
        s[0] = 1.f; s[1] = (obs == 0) ? 1.f : -1.f;
        s[2] = -s[1]; s[3] = -1.f;

        float ReA[4][4];
        for (int j = 0; j < 4; j++)
            for (int m = 0; m < 4; m++) {
                float acc = 0.f;
                for (int k = 0; k < 4; k++)
                    acc += s[k] * (Wr[k][j]*Wr[k][m] + Wi[k][j]*Wi[k][m]);
                ReA[j][m] = acc;
            }

        float M[3][3] = {};
        for (int a = 0; a < 2; a++)
            for (int b = 0; b < 2; b++)
                for (int c = 0; c < 2; c++)
                    for (int d = 0; d < 2; d++)
                        for (int al = 0; al < 3; al++)
                            for (int be = 0; be < 3; be++)
                                M[al][be] += ReA[2*a+c][2*b+d]
                                           * Qu[a][b][al] * Qu[c][d][be];

        for (int al = 0; al < 3; al++)
            for (int be = 0; be < 3; be++)
                g_M[obs * 9 + al * 3 + be] = M[al][be];
    }
    g_M[18] = 0.f;
    g_M[19] = 0.f;
}

__device__ __forceinline__ float bil(const float* m,
                                     float X0, float Y0, float X1, float Y1) {
    float d0 = fmaf(m[2], Y1, fmaf(m[1], X1, m[0]));
    float d1 = fmaf(m[5], Y1, fmaf(m[4], X1, m[3]));
    float d2 = fmaf(m[8], Y1, fmaf(m[7], X1, m[6]));
    return fmaf(Y0, d2, fmaf(X0, d1, d0));
}

__device__ __forceinline__ float4 eval_f4(float4 nz) {
    const float PI = 3.14159265358979323846f;
    float Xa, Ya, Xb, Yb, Xc, Yc, Xd, Yd;
    __sincosf(nz.x * PI, &Ya, &Xa);
    __sincosf(nz.y * PI, &Yb, &Xb);
    __sincosf(nz.z * PI, &Yc, &Xc);
    __sincosf(nz.w * PI, &Yd, &Xd);
    float4 res;
    res.x = bil(c_M + 0, Xa, Ya, Xb, Yb);
    res.y = bil(c_M + 9, Xa, Ya, Xb, Yb);
    res.z = bil(c_M + 0, Xc, Yc, Xd, Yd);
    res.w = bil(c_M + 9, Xc, Yc, Xd, Yd);
    return res;
}

// 4 samples per thread: two independent float4 streams at idx and idx+t
// (both coalesced), loads issued back-to-back -> memory MLP = 2 per thread.
// M in the constant bank (LDCU uniform port, zero L1tex traffic).
__global__ void __launch_bounds__(256) qcirc_kernel(
    const float4* __restrict__ noise, float4* __restrict__ out, int t)
{
    int idx = blockIdx.x * blockDim.x + threadIdx.x;
    if (idx >= t) return;

    // Two independent 128-bit loads, back-to-back (MLP=2).
    float4 a = noise[idx];
    float4 b = noise[idx + t];

    float4 ra = eval_f4(a);
    float4 rb = eval_f4(b);

    out[idx] = ra;
    out[idx + t] = rb;
}

extern "C" void kernel_launch(void* const* d_in, const int* in_sizes, int n_in,
                              void* d_out, int out_size) {
    const float* noise = (const float*)d_in[0];     // [B, 2] f32
    const float* qw    = (const float*)d_in[1];     // [2, 2, 3] f32

    // Node 1: compute the 18 bilinear coefficients.
    prep_kernel<<<1, 32>>>(qw);

    // Node 2: 80-byte device-to-device copy into constant bank (capturable).
    void* gm_addr = nullptr;
    cudaGetSymbolAddress(&gm_addr, g_M);
    cudaMemcpyToSymbolAsync(c_M, gm_addr, 20 * sizeof(float), 0,
                            cudaMemcpyDeviceToDevice, 0);

    // Node 3: bulk evaluation, 4 samples per thread.
    int n4 = in_sizes[0] / 4;   // float4 count
    int t = n4 / 2;             // threads; each handles float4 idx and idx+t
    int threads = 256;
    int blocks = (t + threads - 1) / threads;
    qcirc_kernel<<<blocks, threads>>>(
        (const float4*)noise, (float4*)d_out, t);
}

// round 11
// speedup vs baseline: 1.1866x; 1.1866x over previous
#include <cuda_runtime.h>

// Single self-contained kernel. Each CTA's warp 0 computes the two real 3x3
// bilinear forms M (observables Z0, Z1) cooperatively from q_weights into
// shared memory (~450 cycles, fully parallel, no global state, no
// inter-block sync), then all threads evaluate 4 samples each:
//   z_k = (1, X0, Y0) * M_k * (1, X1, Y1)^T,  X = cos(pi*n), Y = sin(pi*n).

__device__ __forceinline__ float bil(const float* m,
                                     float X0, float Y0, float X1, float Y1) {
    float d0 = fmaf(m[2], Y1, fmaf(m[1], X1, m[0]));
    float d1 = fmaf(m[5], Y1, fmaf(m[4], X1, m[3]));
    float d2 = fmaf(m[8], Y1, fmaf(m[7], X1, m[6]));
    return fmaf(Y0, d2, fmaf(X0, d1, d0));
}

__global__ void __launch_bounds__(256) qcirc_kernel(
    const float4* __restrict__ noise, float4* __restrict__ out,
    const float* __restrict__ qw, int t)
{
    __shared__ float sc[12], ss[12];        // sincos of the 12 half-angles
    __shared__ float sgr[16], sgi[16];      // gate entries (l,w,i,j)
    __shared__ float sWr[16], sWi[16];      // final W (row r, col m)
    __shared__ float sReA[32];              // Re(W^H S W), 2 obs x 16
    __shared__ __align__(16) float sM[20];  // output bilinear forms

    const unsigned FULL = 0xFFFFFFFFu;
    int tid = threadIdx.x;

    if (tid < 32) {
        int lane = tid;

        // ---- Stage 1: 12 sincos in parallel -------------------------------
        if (lane < 12) {
            int l = lane / 6, rem = lane % 6, w = rem / 3, k = rem % 3;
            float phi = qw[l * 6 + w * 3 + 0];
            float th  = qw[l * 6 + w * 3 + 1];
            float om  = qw[l * 6 + w * 3 + 2];
            float ang = (k == 0) ? 0.5f * th
                      : (k == 1) ? 0.5f * (phi + om)
                                 : 0.5f * (phi - om);
            float s, c;
            __sincosf(ang, &s, &c);
            sc[lane] = c; ss[lane] = s;
        }
        __syncwarp(FULL);

        // ---- Stage 2: 16 gate entries in parallel -------------------------
        // Rot = RZ(om) RY(th) RZ(phi):
        //  (0,0)=( ct*ca, -ct*sa)  (0,1)=(-st*cb, -st*sb)
        //  (1,0)=( st*cb, -st*sb)  (1,1)=( ct*ca,  ct*sa)
        if (lane < 16) {
            int l = lane >> 3, w = (lane >> 2) & 1, i = (lane >> 1) & 1, j = lane & 1;
            int base = l * 6 + w * 3;
            float ct = sc[base + 0], st = ss[base + 0];
            float ca = sc[base + 1], sa = ss[base + 1];
            float cb = sc[base + 2], sb = ss[base + 2];
            float re = (i == j) ? ct * ca : ((i == 0) ? -st * cb : st * cb);
            float im = (i == 0) ? ((j == 0) ? -ct * sa : -st * sb)
                                : ((j == 0) ? -st * sb :  ct * sa);
            sgr[lane] = re; sgi[lane] = im;
        }
        __syncwarp(FULL);

        // ---- Stage 3: W evolution, one complex entry per lane -------------
        // q = r*4 + m, r = basis row (i*2+j), m = column. Lanes 16-31 mirror.
        int q = lane & 15;
        int r = q >> 2, m = q & 3;
        int i = r >> 1, j = r & 1;
        // W init = D = diag(1, -i, -i, -1)
        float wr = (q == 0) ? 1.f : ((q == 15) ? -1.f : 0.f);
        float wi = (q == 5 || q == 10) ? -1.f : 0.f;

        #pragma unroll
        for (int l = 0; l < 2; l++) {
            // Gate on qubit 0: new(i,j) = g0[i][0]*W(0,j) + g0[i][1]*W(1,j)
            {
                float ar = __shfl_sync(FULL, wr, j * 4 + m);
                float ai = __shfl_sync(FULL, wi, j * 4 + m);
                float br = __shfl_sync(FULL, wr, (2 + j) * 4 + m);
                float bi = __shfl_sync(FULL, wi, (2 + j) * 4 + m);
                int c0 = (l * 2 + 0) * 4 + i * 2;
                float g0r = sgr[c0],     g0i = sgi[c0];
                float g1r = sgr[c0 + 1], g1i = sgi[c0 + 1];
                wr = g0r * ar - g0i * ai + g1r * br - g1i * bi;
                wi = g0r * ai + g0i * ar + g1r * bi + g1i * br;
            }
            // Gate on qubit 1: new(i,j) = g1[j][0]*W(i,0) + g1[j][1]*W(i,1)
            {
                float ar = __shfl_sync(FULL, wr, (2 * i) * 4 + m);
                float ai = __shfl_sync(FULL, wi, (2 * i) * 4 + m);
                float br = __shfl_sync(FULL, wr, (2 * i + 1) * 4 + m);
                float bi = __shfl_sync(FULL, wi, (2 * i + 1) * 4 + m);
                int c0 = (l * 2 + 1) * 4 + j * 2;
                float g0r = sgr[c0],     g0i = sgi[c0];
                float g1r = sgr[c0 + 1], g1i = sgi[c0 + 1];
                wr = g0r * ar - g0i * ai + g1r * br - g1i * bi;
                wi = g0r * ai + g0i * ar + g1r * bi + g1i * br;
            }
            // Fused CNOT(0->1) then CNOT(1->0): new(i,j) = old(i^j, i)
            {
                int sp = ((i ^ j) * 2 + i) * 4 + m;
                float nwr = __shfl_sync(FULL, wr, sp);
                float nwi = __shfl_sync(FULL, wi, sp);
                wr = nwr; wi = nwi;
            }
        }
        if (lane < 16) { sWr[q] = wr; sWi[q] = wi; }
        __syncwarp(FULL);

        // ---- Stage 4: ReA[j][m] = Re((W^H S W))[j][m], one per lane -------
        {
            int obs = lane >> 4, jj = (lane >> 2) & 3, mm = lane & 3;
            float acc = 0.f;
            #pragma unroll
            for (int k = 0; k < 4; k++) {
                float sk = (obs == 0) ? ((k < 2) ? 1.f : -1.f)
                                      : ((k & 1) ? -1.f : 1.f);
                acc += sk * (sWr[k * 4 + jj] * sWr[k * 4 + mm]
                           + sWi[k * 4 + jj] * sWi[k * 4 + mm]);
            }
            sReA[lane] = acc;
        }
        __syncwarp(FULL);

        // ---- Stage 5: project onto (1,X,Y) x (1,X,Y), one M entry/lane ----
        // Qu sparsity: index e has two (a,b,sign) pairs:
        //  e=0: (0,0,+),(1,1,+)  e=1: (0,0,+),(1,1,-)  e=2: (0,1,+),(1,0,+)
        if (lane < 20) {
            if (lane < 18) {
                const int   A0[3] = {0, 0, 0}, B0[3] = {0, 0, 1};
                const int   A1[3] = {1, 1, 1}, B1[3] = {1, 1, 0};
                const float S1[3] = {1.f, -1.f, 1.f};
                int obs = lane / 9, e = lane % 9, al = e / 3, be = e % 3;
                const float* Rbase = sReA + obs * 16;
                float acc = 0.f;
                #pragma unroll
                for (int p = 0; p < 2; p++) {
                    int ap = p ? A1[al] : A0[al];
                    int bp = p ? B1[al] : B0[al];
                    float sp = p ? S1[al] : 1.f;
                    #pragma unroll
                    for (int qq = 0; qq < 2; qq++) {
                        int aq = qq ? A1[be] : A0[be];
                        int bq = qq ? B1[be] : B0[be];
                        float sq = qq ? S1[be] : 1.f;
                        acc += sp * sq * Rbase[(2 * ap + aq) * 4 + (2 * bp + bq)];
                    }
                }
                sM[lane] = 0.25f * acc;
            } else {
                sM[lane] = 0.f;
            }
        }
    }
    __syncthreads();

    // ---- Hot path: 4 samples/thread, two coalesced float4 streams ---------
    int idx = blockIdx.x * blockDim.x + tid;
    if (idx >= t) return;

    float4 a = noise[idx];
    float4 b = noise[idx + t];

    // 5 x LDS.128 broadcast (conflict-free), M uniform per block.
    float M[20];
    const float4* sp4 = reinterpret_cast<const float4*>(sM);
    #pragma unroll
    for (int k = 0; k < 5; k++) {
        float4 v = sp4[k];
        M[4 * k + 0] = v.x; M[4 * k + 1] = v.y;
        M[4 * k + 2] = v.z; M[4 * k + 3] = v.w;
    }

    const float PI = 3.14159265358979323846f;
    float Xa, Ya, Xb, Yb, Xc, Yc, Xd, Yd;
    float4 ra, rb;

    __sincosf(a.x * PI, &Ya, &Xa);
    __sincosf(a.y * PI, &Yb, &Xb);
    __sincosf(a.z * PI, &Yc, &Xc);
    __sincosf(a.w * PI, &Yd, &Xd);
    ra.x = bil(M + 0, Xa, Ya, Xb, Yb);
    ra.y = bil(M + 9, Xa, Ya, Xb, Yb);
    ra.z = bil(M + 0, Xc, Yc, Xd, Yd);
    ra.w = bil(M + 9, Xc, Yc, Xd, Yd);

    __sincosf(b.x * PI, &Ya, &Xa);
    __sincosf(b.y * PI, &Yb, &Xb);
    __sincosf(b.z * PI, &Yc, &Xc);
    __sincosf(b.w * PI, &Yd, &Xd);
    rb.x = bil(M + 0, Xa, Ya, Xb, Yb);
    rb.y = bil(M + 9, Xa, Ya, Xb, Yb);
    rb.z = bil(M + 0, Xc, Yc, Xd, Yd);
    rb.w = bil(M + 9, Xc, Yc, Xd, Yd);

    out[idx] = ra;
    out[idx + t] = rb;
}

extern "C" void kernel_launch(void* const* d_in, const int* in_sizes, int n_in,
                              void* d_out, int out_size) {
    const float* noise = (const float*)d_in[0];     // [B, 2] f32
    const float* qw    = (const float*)d_in[1];     // [2, 2, 3] f32

    int n4 = in_sizes[0] / 4;   // float4 count
    int t = n4 / 2;             // threads; each handles float4 idx and idx+t
    int threads = 256;
    int blocks = (t + threads - 1) / threads;
    qcirc_kernel<<<blocks, threads>>>(
        (const float4*)noise, (float4*)d_out, qw, t);
}